// round 2
// baseline (speedup 1.0000x reference)
#include <cuda_runtime.h>
#include <math_constants.h>

#define NPTS   8192
#define WID    8193
#define CHUNK  1024
#define NCH    65536          // 8192 rows * 8 chunks, row-major chunk order
#define NT     64
#define KCORR  2048
#define MAXC   8192
#define MARGIN 1e-4f
#define CHEPS  1e-3f
#define CAP    (1 << 18)

// ---------------- device scratch (no allocations allowed) ----------------
__device__ float    d_table[NT];
__device__ float    d_logt[NT];
__device__ float    d_logr[NPTS];
__device__ float    d_logs[NPTS];
__device__ float    d_chunkmax[NCH];
__device__ unsigned d_chist[NT];
__device__ float    d_cutL;
__device__ unsigned d_ccnt[NCH];
__device__ unsigned d_coff[NCH];
__device__ unsigned d_ncand;
__device__ unsigned d_ckey[CAP];
__device__ float    d_cv[CAP];
__device__ float    d_thres;

// ---------------- K0: tables + logs + zero hist ----------------
__global__ void k_init(const float* __restrict__ ref, const float* __restrict__ src) {
    int i = blockIdx.x * 256 + threadIdx.x;
    if (i < NPTS) { d_logr[i] = logf(ref[i]); d_logs[i] = logf(src[i]); }
    if (i < NT) d_chist[i] = 0u;
    if (i == 0) {
        float t = 0.5f;  // exact replication of fp32 t -= 0.01f iteration
        for (int n = 0; n < NT; ++n) {
            d_table[n] = t;
            d_logt[n]  = (t > 0.0f) ? logf(t) : -1e30f;
            t = t - 0.01f;
        }
    }
}

// ---------------- K1: the single full 268MB pass ----------------
// grid 1024: bx&7 = column-chunk, bx>>3 = group of 64 rows; 8 warps x 8 rows.
__global__ void __launch_bounds__(256) k_chunkmax(const float* __restrict__ ms) {
    __shared__ float s_ls[CHUNK];
    const int c = blockIdx.x & 7, rg = blockIdx.x >> 3;
    for (int i = threadIdx.x; i < CHUNK; i += 256) s_ls[i] = d_logs[c * CHUNK + i];
    __syncthreads();
    const int lane = threadIdx.x & 31, w = threadIdx.x >> 5;
    for (int rr = 0; rr < 8; ++rr) {
        const int row = rg * 64 + w * 8 + rr;
        const float* p = ms + (size_t)row * WID + c * CHUNK + lane;
        float m = -CUDART_INF_F;
#pragma unroll
        for (int it = 0; it < 32; ++it)
            m = fmaxf(m, p[it * 32] + s_ls[it * 32 + lane]);
        m += d_logr[row];
#pragma unroll
        for (int o = 16; o; o >>= 1)
            m = fmaxf(m, __shfl_xor_sync(0xffffffffu, m, o));
        if (lane == 0) d_chunkmax[row * 8 + c] = m;
    }
}

// ---------------- K2: bracket threshold from chunk maxima ----------------
__global__ void k_chunkbin() {
    int i = blockIdx.x * 256 + threadIdx.x;
    float m = d_chunkmax[i];
    int lo = 0, hi = NT;                       // first n with logt[n]+MARGIN < m
    while (lo < hi) { int mid = (lo + hi) >> 1; if (d_logt[mid] + MARGIN < m) hi = mid; else lo = mid + 1; }
    if (lo < NT) atomicAdd(&d_chist[lo], 1u);
}

__global__ void k_picknlow() {
    unsigned cum = 0; int nl = NT - 1;
    for (int n = 0; n < NT; ++n) { cum += d_chist[n]; if (cum >= KCORR) { nl = n; break; } }
    d_cutL = d_logt[nl] - MARGIN;              // all elements that can matter have L > cutL
}

// ---------------- sparse chunk walk (count / ordered extract) ----------------
__device__ __forceinline__ unsigned chunk_pass(
    const float* __restrict__ ms, const float* __restrict__ ref, const float* __restrict__ src,
    int task, int lane, float cutL, unsigned base, bool write)
{
    const int row = task >> 3, c = task & 7;
    const float lr = d_logr[row];
    const float* p = ms + (size_t)row * WID + c * CHUNK + lane;
    unsigned cnt = 0;
    for (int it = 0; it < 32; ++it) {
        const int col = c * CHUNK + it * 32 + lane;
        const float msv = p[it * 32];
        const float L = (msv + d_logs[col]) + lr;
        const bool pred = L > cutL;
        const unsigned mk = __ballot_sync(0xffffffffu, pred);
        if (pred && write) {
            unsigned pos = base + cnt + __popc(mk & ((1u << lane) - 1u));
            if (pos < CAP) {
                d_ckey[pos] = ((unsigned)row << 13) | (unsigned)col;
                d_cv[pos]   = expf(msv) * (ref[row] * src[col]);   // exact reference expression
            }
        }
        cnt += __popc(mk);
    }
    return cnt;
}

__global__ void k_countcand(const float* __restrict__ ms, const float* __restrict__ ref,
                            const float* __restrict__ src) {
    const int lane = threadIdx.x & 31;
    const int gw = (blockIdx.x * blockDim.x + threadIdx.x) >> 5;
    const int nw = (gridDim.x * blockDim.x) >> 5;
    const float cutL = d_cutL;
    for (int task = gw; task < NCH; task += nw) {
        unsigned c = 0;
        if (d_chunkmax[task] > cutL - CHEPS)
            c = chunk_pass(ms, ref, src, task, lane, cutL, 0u, false);
        if (lane == 0) d_ccnt[task] = c;
    }
}

// ---------------- K4: single-block scan of 65536 chunk counts ----------------
__global__ void __launch_bounds__(1024) k_scan() {
    __shared__ unsigned ws[32];
    const int t = threadIdx.x, lane = t & 31, wid = t >> 5;
    unsigned s = 0;
    for (int j = 0; j < 64; ++j) s += d_ccnt[t * 64 + j];
    unsigned x = s;
#pragma unroll
    for (int o = 1; o < 32; o <<= 1) { unsigned y = __shfl_up_sync(0xffffffffu, x, o); if (lane >= o) x += y; }
    if (lane == 31) ws[wid] = x;
    __syncthreads();
    if (wid == 0) {
        unsigned v = ws[lane], y = v;
#pragma unroll
        for (int o = 1; o < 32; o <<= 1) { unsigned z = __shfl_up_sync(0xffffffffu, y, o); if (lane >= o) y += z; }
        ws[lane] = y - v;
        if (lane == 31) d_ncand = y;
    }
    __syncthreads();
    unsigned base = (x - s) + ws[wid];
    for (int j = 0; j < 64; ++j) { unsigned cc = d_ccnt[t * 64 + j]; d_coff[t * 64 + j] = base; base += cc; }
}

__global__ void k_extract(const float* __restrict__ ms, const float* __restrict__ ref,
                          const float* __restrict__ src) {
    const int lane = threadIdx.x & 31;
    const int gw = (blockIdx.x * blockDim.x + threadIdx.x) >> 5;
    const int nw = (gridDim.x * blockDim.x) >> 5;
    const float cutL = d_cutL;
    for (int task = gw; task < NCH; task += nw) {
        if (d_chunkmax[task] > cutL - CHEPS)
            chunk_pass(ms, ref, src, task, lane, cutL, d_coff[task], true);
    }
}

// ---------------- K5: exact threshold from candidate values ----------------
__global__ void __launch_bounds__(1024) k_pickthres() {
    __shared__ unsigned h[NT];
    __shared__ float tt[NT];
    if (threadIdx.x < NT) { h[threadIdx.x] = 0u; tt[threadIdx.x] = d_table[threadIdx.x]; }
    __syncthreads();
    const unsigned n = min(d_ncand, (unsigned)CAP);
    for (unsigned i = threadIdx.x; i < n; i += 1024) {
        const float v = d_cv[i];
        int lo = 0, hi = NT - 1;                 // first n with table[n] < v
        while (lo < hi) { int mid = (lo + hi) >> 1; if (tt[mid] < v) hi = mid; else lo = mid + 1; }
        atomicAdd(&h[lo], 1u);
    }
    __syncthreads();
    if (threadIdx.x == 0) {
        unsigned cum = 0; int pick = NT - 1;
        for (int i = 0; i < NT; ++i) { cum += h[i]; if (cum >= KCORR) { pick = i; break; } }
        d_thres = d_table[pick];
    }
}

// ---------------- K6: ordered compaction + padding ----------------
__global__ void __launch_bounds__(1024) k_output(float* __restrict__ out, int seg) {
    __shared__ unsigned ws[32];
    __shared__ unsigned s_tot;
    const float thres = d_thres;
    const unsigned n = min(d_ncand, (unsigned)CAP);
    const int lane = threadIdx.x & 31, wid = threadIdx.x >> 5;
    const unsigned lim = (unsigned)min(seg, MAXC);
    unsigned base = 0;
    for (unsigned start = 0; start < n; start += 1024) {
        const unsigned i = start + threadIdx.x;
        bool pred = false; float v = 0.0f; unsigned key = 0;
        if (i < n) { v = d_cv[i]; key = d_ckey[i]; pred = (v > thres); }
        unsigned x = pred ? 1u : 0u, p = x;
#pragma unroll
        for (int o = 1; o < 32; o <<= 1) { unsigned y = __shfl_up_sync(0xffffffffu, p, o); if (lane >= o) p += y; }
        if (lane == 31) ws[wid] = p;
        __syncthreads();
        if (wid == 0) {
            unsigned w0 = ws[lane], y = w0;
#pragma unroll
            for (int o = 1; o < 32; o <<= 1) { unsigned z = __shfl_up_sync(0xffffffffu, y, o); if (lane >= o) y += z; }
            ws[lane] = y - w0;
            if (lane == 31) s_tot = y;
        }
        __syncthreads();
        const unsigned slot = base + (p - x) + ws[wid];
        if (pred && slot < lim) {
            out[slot]           = (float)(key >> 13);
            out[seg + slot]     = (float)(key & 8191u);
            out[2 * seg + slot] = v;
        }
        base += s_tot;
        __syncthreads();
    }
    // padding: valid = idx < count  ->  slots >= min(count, seg) get (-1,-1,0)
    for (unsigned i = min(base, lim) + threadIdx.x; i < (unsigned)seg; i += 1024) {
        out[i] = -1.0f; out[seg + i] = -1.0f; out[2 * seg + i] = 0.0f;
    }
}

// ---------------- launch ----------------
extern "C" void kernel_launch(void* const* d_in, const int* in_sizes, int n_in,
                              void* d_out, int out_size) {
    const float* ms  = (const float*)d_in[0];
    const float* ref = (const float*)d_in[1];
    const float* src = (const float*)d_in[2];
    float* out = (float*)d_out;
    const int seg = out_size / 3;

    k_init     <<<32, 256>>>(ref, src);
    k_chunkmax <<<1024, 256>>>(ms);
    k_chunkbin <<<256, 256>>>();
    k_picknlow <<<1, 1>>>();
    k_countcand<<<256, 256>>>(ms, ref, src);
    k_scan     <<<1, 1024>>>();
    k_extract  <<<256, 256>>>(ms, ref, src);
    k_pickthres<<<1, 1024>>>();
    k_output   <<<1, 1024>>>(out, seg);
}

// round 3
// speedup vs baseline: 1.9597x; 1.9597x over previous
#include <cuda_runtime.h>
#include <math_constants.h>

#define NPTS   8192
#define WID    8193
#define CHUNK  1024
#define NCH    65536          // 8192 rows * 8 chunks, row-major chunk order
#define NT     64
#define KCORR  2048
#define MARGIN 1e-4f
#define CAP    (1 << 19)

// ---------------- device scratch (no allocations allowed) ----------------
__device__ float    d_table[NT];
__device__ float    d_logt[NT];
__device__ float    d_logr[NPTS];
__device__ float    d_logs[NPTS];
__device__ float    d_chunkmax[NCH];
__device__ unsigned d_chist[NT];
__device__ float    d_cutL;
__device__ unsigned d_ccnt[NCH];
__device__ unsigned d_coff[NCH];
__device__ unsigned d_ncand;
__device__ unsigned d_ckey[CAP];
__device__ float    d_cv[CAP];

// ---------------- K0: tables + logs + zero hist ----------------
__global__ void k_init(const float* __restrict__ ref, const float* __restrict__ src) {
    int i = blockIdx.x * 256 + threadIdx.x;
    if (i < NPTS) { d_logr[i] = logf(ref[i]); d_logs[i] = logf(src[i]); }
    if (i < NT) d_chist[i] = 0u;
    if (i == 0) {
        float t = 0.5f;  // exact replication of fp32 t -= 0.01f iteration
        for (int n = 0; n < NT; ++n) {
            d_table[n] = t;
            d_logt[n]  = (t > 0.0f) ? logf(t) : -1e30f;
            t = t - 0.01f;
        }
    }
}

// ---------------- K1: the single full 268MB pass (+fused chunk hist) -------
// grid 1024: bx&7 = column-chunk, bx>>3 = group of 64 rows; 8 warps x 8 rows.
__global__ void __launch_bounds__(256) k_chunkmax(const float* __restrict__ ms) {
    __shared__ float s_ls[CHUNK];
    const int c = blockIdx.x & 7, rg = blockIdx.x >> 3;
    for (int i = threadIdx.x; i < CHUNK; i += 256) s_ls[i] = d_logs[c * CHUNK + i];
    __syncthreads();
    const int lane = threadIdx.x & 31, w = threadIdx.x >> 5;
    for (int rr = 0; rr < 8; ++rr) {
        const int row = rg * 64 + w * 8 + rr;
        const float* p = ms + (size_t)row * WID + c * CHUNK + lane;
        const float lr = d_logr[row];
        float m = -CUDART_INF_F;
#pragma unroll
        for (int it = 0; it < 32; ++it)
            m = fmaxf(m, (p[it * 32] + s_ls[it * 32 + lane]) + lr);
#pragma unroll
        for (int o = 16; o; o >>= 1)
            m = fmaxf(m, __shfl_xor_sync(0xffffffffu, m, o));
        if (lane == 0) {
            d_chunkmax[row * 8 + c] = m;
            int lo = 0, hi = NT;      // first n with logt[n]+MARGIN < m
            while (lo < hi) { int mid = (lo + hi) >> 1; if (d_logt[mid] + MARGIN < m) hi = mid; else lo = mid + 1; }
            if (lo < NT) atomicAdd(&d_chist[lo], 1u);
        }
    }
}

// ---------------- K2: bracket threshold pick (smem, 1 block) ----------------
__global__ void k_picknlow() {
    __shared__ unsigned s[NT];
    const int t = threadIdx.x;
    if (t < NT) s[t] = d_chist[t];
    __syncthreads();
    if (t == 0) {
        unsigned cum = 0; int nl = NT - 1;
        for (int n = 0; n < NT; ++n) { cum += s[n]; if (cum >= KCORR) { nl = n; break; } }
        d_cutL = d_logt[nl] - MARGIN;
    }
}

// ---------------- K3: per-chunk candidate count (warp-per-chunk) ------------
__global__ void __launch_bounds__(256) k_countcand(const float* __restrict__ ms) {
    const int gw   = (blockIdx.x * 256 + threadIdx.x) >> 5;
    const int lane = threadIdx.x & 31;
    const float cutL = d_cutL;
    unsigned cnt = 0;
    if (d_chunkmax[gw] > cutL) {
        const int row = gw >> 3, ch = gw & 7;
        const float lr = d_logr[row];
        const float* p  = ms     + (size_t)row * WID + ch * CHUNK + lane;
        const float* ls = d_logs + ch * CHUNK + lane;
        unsigned pb = 0;
#pragma unroll
        for (int it = 0; it < 32; ++it) {
            const float L = (p[it * 32] + ls[it * 32]) + lr;   // same assoc as chunkmax
            pb |= (L > cutL) ? (1u << it) : 0u;
        }
        cnt = (unsigned)__popc(pb);
#pragma unroll
        for (int o = 16; o; o >>= 1) cnt += __shfl_xor_sync(0xffffffffu, cnt, o);
    }
    if (lane == 0) d_ccnt[gw] = cnt;
}

// ---------------- K4: single-block scan of 65536 chunk counts ----------------
__global__ void __launch_bounds__(1024) k_scan() {
    __shared__ unsigned ws[32];
    const int t = threadIdx.x, lane = t & 31, wid = t >> 5;
    const uint4* cc4 = (const uint4*)d_ccnt;
    unsigned s = 0;
#pragma unroll
    for (int j = 0; j < 16; ++j) {
        uint4 v = cc4[t * 16 + j];
        s += v.x + v.y + v.z + v.w;
    }
    unsigned x = s;
#pragma unroll
    for (int o = 1; o < 32; o <<= 1) { unsigned y = __shfl_up_sync(0xffffffffu, x, o); if (lane >= o) x += y; }
    if (lane == 31) ws[wid] = x;
    __syncthreads();
    if (wid == 0) {
        unsigned v = ws[lane], y = v;
#pragma unroll
        for (int o = 1; o < 32; o <<= 1) { unsigned z = __shfl_up_sync(0xffffffffu, y, o); if (lane >= o) y += z; }
        ws[lane] = y - v;
        if (lane == 31) d_ncand = y;
    }
    __syncthreads();
    unsigned base = (x - s) + ws[wid];
    uint4* co4 = (uint4*)d_coff;
#pragma unroll
    for (int j = 0; j < 16; ++j) {
        uint4 v = cc4[t * 16 + j];
        uint4 o;
        o.x = base; base += v.x;
        o.y = base; base += v.y;
        o.z = base; base += v.z;
        o.w = base; base += v.w;
        co4[t * 16 + j] = o;
    }
}

// ---------------- K5: ordered candidate extraction (warp-per-chunk) ---------
__global__ void __launch_bounds__(256) k_extract(const float* __restrict__ ms,
                                                 const float* __restrict__ ref,
                                                 const float* __restrict__ src) {
    const int gw   = (blockIdx.x * 256 + threadIdx.x) >> 5;
    const int lane = threadIdx.x & 31;
    const float cutL = d_cutL;
    if (!(d_chunkmax[gw] > cutL)) return;       // warp-uniform
    const int row = gw >> 3, ch = gw & 7;
    const float lr = d_logr[row];
    const float* p  = ms     + (size_t)row * WID + ch * CHUNK + lane;
    const float* ls = d_logs + ch * CHUNK + lane;
    float msv[32];
    unsigned pb = 0;
#pragma unroll
    for (int it = 0; it < 32; ++it) {
        msv[it] = p[it * 32];
        const float L = (msv[it] + ls[it * 32]) + lr;
        pb |= (L > cutL) ? (1u << it) : 0u;
    }
    const unsigned base = d_coff[gw];
    const float rr = ref[row];
    unsigned cnt = 0;
#pragma unroll
    for (int it = 0; it < 32; ++it) {
        const bool pred = (pb >> it) & 1u;
        const unsigned mk = __ballot_sync(0xffffffffu, pred);
        if (pred) {
            const unsigned pos = base + cnt + __popc(mk & ((1u << lane) - 1u));
            if (pos < CAP) {
                const int col = ch * CHUNK + it * 32 + lane;
                d_ckey[pos] = ((unsigned)row << 13) | (unsigned)col;
                d_cv[pos]   = expf(msv[it]) * (rr * src[col]);   // exact reference expr
            }
        }
        cnt += (unsigned)__popc(mk);
    }
}

// ---------------- K6: fused exact-threshold pick + ordered output ------------
__global__ void __launch_bounds__(1024) k_finish(float* __restrict__ out, int seg) {
    __shared__ unsigned h[NT];
    __shared__ float    tt[NT];
    __shared__ unsigned ws[32];
    __shared__ float    s_thres;
    __shared__ unsigned s_tot;
    const int t = threadIdx.x, lane = t & 31, wid = t >> 5;
    if (t < NT) { h[t] = 0u; tt[t] = d_table[t]; }
    __syncthreads();
    const unsigned n = min(d_ncand, (unsigned)CAP);

    // exact element histogram over candidates (linear domain)
    for (unsigned i = t; i < n; i += 1024) {
        const float v = d_cv[i];
        int lo = 0, hi = NT - 1;                // first n with table[n] < v
        while (lo < hi) { int mid = (lo + hi) >> 1; if (tt[mid] < v) hi = mid; else lo = mid + 1; }
        atomicAdd(&h[lo], 1u);
    }
    __syncthreads();
    if (t == 0) {
        unsigned cum = 0; int pick = NT - 1;
        for (int i = 0; i < NT; ++i) { cum += h[i]; if (cum >= KCORR) { pick = i; break; } }
        s_thres = d_table[pick];
    }
    __syncthreads();
    const float thres = s_thres;
    const unsigned lim = (unsigned)min(seg, 8192);

    // ordered compaction, 4 elements per thread per tile
    unsigned base = 0;
    for (unsigned start = 0; start < n; start += 4096) {
        float v4[4]; unsigned k4[4]; bool pr[4];
        const unsigned i0 = start + (unsigned)t * 4u;
        unsigned pc = 0;
#pragma unroll
        for (int j = 0; j < 4; ++j) {
            const unsigned i = i0 + j;
            pr[j] = false;
            if (i < n) { v4[j] = d_cv[i]; k4[j] = d_ckey[i]; pr[j] = (v4[j] > thres); pc += pr[j] ? 1u : 0u; }
        }
        unsigned x = pc;
#pragma unroll
        for (int o = 1; o < 32; o <<= 1) { unsigned y = __shfl_up_sync(0xffffffffu, x, o); if (lane >= o) x += y; }
        if (lane == 31) ws[wid] = x;
        __syncthreads();
        if (wid == 0) {
            unsigned v = ws[lane], y = v;
#pragma unroll
            for (int o = 1; o < 32; o <<= 1) { unsigned z = __shfl_up_sync(0xffffffffu, y, o); if (lane >= o) y += z; }
            ws[lane] = y - v;
            if (lane == 31) s_tot = y;
        }
        __syncthreads();
        unsigned slot = base + (x - pc) + ws[wid];
#pragma unroll
        for (int j = 0; j < 4; ++j) {
            if (pr[j]) {
                if (slot < lim) {
                    out[slot]           = (float)(k4[j] >> 13);
                    out[seg + slot]     = (float)(k4[j] & 8191u);
                    out[2 * seg + slot] = v4[j];
                }
                ++slot;
            }
        }
        base += s_tot;
        __syncthreads();
    }
    // padding: valid = idx < count
    for (unsigned i = min(base, lim) + (unsigned)t; i < (unsigned)seg; i += 1024) {
        out[i] = -1.0f; out[seg + i] = -1.0f; out[2 * seg + i] = 0.0f;
    }
}

// ---------------- launch ----------------
extern "C" void kernel_launch(void* const* d_in, const int* in_sizes, int n_in,
                              void* d_out, int out_size) {
    const float* ms  = (const float*)d_in[0];
    const float* ref = (const float*)d_in[1];
    const float* src = (const float*)d_in[2];
    float* out = (float*)d_out;
    const int seg = out_size / 3;

    k_init     <<<32, 256>>>(ref, src);
    k_chunkmax <<<1024, 256>>>(ms);
    k_picknlow <<<1, 64>>>();
    k_countcand<<<8192, 256>>>(ms);
    k_scan     <<<1, 1024>>>();
    k_extract  <<<8192, 256>>>(ms, ref, src);
    k_finish   <<<1, 1024>>>(out, seg);
}